// round 13
// baseline (speedup 1.0000x reference)
#include <cuda_runtime.h>
#include <cuda_bf16.h>

// Problem constants
#define B_       2
#define NC_      5
#define DHW_     2457600             // 96*160*160
#define N4_      (DHW_/4)            // 614400 float4 groups per (b, channel)
#define THREADS_ 128
#define GRIDX_   320
#define STRIDE_  (GRIDX_ * THREADS_) // 40960 threads per batch slice
#define ITERS_   15                  // 40960 * 15 = 614400 exactly
#define NBLK_    (GRIDX_ * 2)        // 640 blocks

// Scratch: [b][j]:
//  0..15  = S sums (k*4 + c), k=0..3, c=ch-1     16..19 = S per-channel totals
// 20..35  = T sums (20 + k*4 + c)                36..39 = T per-channel totals
// 40..43  = counts k=0..3
// Class-4 sums/counts derived by subtraction in the epilogue.
__device__ double g_acc[B_][44];
__device__ unsigned int g_count = 0;

typedef unsigned long long u64;

__device__ __forceinline__ u64 packf2(float lo, float hi) {
    u64 r; asm("mov.b64 %0, {%1, %2};" : "=l"(r) : "f"(lo), "f"(hi)); return r;
}
__device__ __forceinline__ void unpackf2(u64 v, float& lo, float& hi) {
    asm("mov.b64 {%0, %1}, %2;" : "=f"(lo), "=f"(hi) : "l"(v));
}
__device__ __forceinline__ void addf2(u64& a, u64 b) {
    asm("add.rn.f32x2 %0, %0, %1;" : "+l"(a) : "l"(b));
}
// One setp feeds 5 predicated adds: both tensors' packed sums + the count.
__device__ __forceinline__ void pred_acc5(int g, int k,
                                          u64& s01, u64& s23,
                                          u64& t01, u64& t23, float& n,
                                          u64 sa, u64 sc, u64 ta, u64 tc) {
    asm("{\n\t"
        ".reg .pred p;\n\t"
        "setp.eq.s32 p, %5, %6;\n\t"
        "@p add.rn.f32x2 %0, %0, %7;\n\t"
        "@p add.rn.f32x2 %1, %1, %8;\n\t"
        "@p add.rn.f32x2 %2, %2, %9;\n\t"
        "@p add.rn.f32x2 %3, %3, %10;\n\t"
        "@p add.f32 %4, %4, 0f3F800000;\n\t"
        "}"
        : "+l"(s01), "+l"(s23), "+l"(t01), "+l"(t23), "+f"(n)
        : "r"(g), "r"(k), "l"(sa), "l"(sc), "l"(ta), "l"(tc));
}

// exp(u) for tiny |u| via degree-6 Taylor; libm fallback for robustness.
__device__ __forceinline__ double fast_exp_small(double u) {
    if (fabs(u) > 0.125) return exp(u);
    double r = 1.0 / 720.0;
    r = fma(r, u, 1.0 / 120.0);
    r = fma(r, u, 1.0 / 24.0);
    r = fma(r, u, 1.0 / 6.0);
    r = fma(r, u, 0.5);
    r = fma(r, u, 1.0);
    r = fma(r, u, 1.0);
    return r;
}
// log(es) for es near 4: ln4 + 2*atanh(w).
__device__ __forceinline__ double fast_log_near4(double es) {
    double v = (es - 4.0) * 0.25;
    if (fabs(v) > 0.125) return log(es);
    double w = v / (2.0 + v);
    double w2 = w * w;
    double r = 1.0 / 7.0;
    r = fma(r, w2, 1.0 / 5.0);
    r = fma(r, w2, 1.0 / 3.0);
    r = fma(r, w2, 1.0);
    return fma(2.0 * w, r, 1.3862943611198906188);
}

__global__ __launch_bounds__(THREADS_)
void kd_fused_kernel(const float* __restrict__ src,
                     const float* __restrict__ tgt,
                     const int* __restrict__ gt,
                     float* __restrict__ out) {
    const int b = blockIdx.y;

    // Packed bins: s01/s23[k] = S(ch1,ch2)/(ch3,ch4); same for T; totals; counts
    u64 s01[4], s23[4], t01[4], t23[4];
    u64 sC01 = 0ull, sC23 = 0ull, tC01 = 0ull, tC23 = 0ull;
    float cnt[4];
#pragma unroll
    for (int k = 0; k < 4; k++) {
        s01[k] = 0ull; s23[k] = 0ull; t01[k] = 0ull; t23[k] = 0ull; cnt[k] = 0.f;
    }

    const float* Sb = src + (size_t)b * NC_ * DHW_;
    const float* Tb = tgt + (size_t)b * NC_ * DHW_;
    const float4* s1p = (const float4*)(Sb + 1 * (size_t)DHW_);
    const float4* s2p = (const float4*)(Sb + 2 * (size_t)DHW_);
    const float4* s3p = (const float4*)(Sb + 3 * (size_t)DHW_);
    const float4* s4p = (const float4*)(Sb + 4 * (size_t)DHW_);
    const float4* t1p = (const float4*)(Tb + 1 * (size_t)DHW_);
    const float4* t2p = (const float4*)(Tb + 2 * (size_t)DHW_);
    const float4* t3p = (const float4*)(Tb + 3 * (size_t)DHW_);
    const float4* t4p = (const float4*)(Tb + 4 * (size_t)DHW_);
    const int4* g4 = (const int4*)(gt + (size_t)b * DHW_);

    const int tid0 = blockIdx.x * THREADS_ + threadIdx.x;

#pragma unroll 1
    for (int j = 0; j < ITERS_; j++) {
        const int i = tid0 + j * STRIDE_;   // exact tiling, no bounds check
        int4   g  = __ldcs(g4 + i);
        float4 a1 = __ldcs(s1p + i);
        float4 a2 = __ldcs(s2p + i);
        float4 a3 = __ldcs(s3p + i);
        float4 a4 = __ldcs(s4p + i);
        float4 b1 = __ldcs(t1p + i);
        float4 b2 = __ldcs(t2p + i);
        float4 b3 = __ldcs(t3p + i);
        float4 b4 = __ldcs(t4p + i);

        {
            u64 sa = packf2(a1.x, a2.x), sc = packf2(a3.x, a4.x);
            u64 ta = packf2(b1.x, b2.x), tc = packf2(b3.x, b4.x);
            addf2(sC01, sa); addf2(sC23, sc); addf2(tC01, ta); addf2(tC23, tc);
#pragma unroll
            for (int k = 0; k < 4; k++)
                pred_acc5(g.x, k, s01[k], s23[k], t01[k], t23[k], cnt[k], sa, sc, ta, tc);
        }
        {
            u64 sa = packf2(a1.y, a2.y), sc = packf2(a3.y, a4.y);
            u64 ta = packf2(b1.y, b2.y), tc = packf2(b3.y, b4.y);
            addf2(sC01, sa); addf2(sC23, sc); addf2(tC01, ta); addf2(tC23, tc);
#pragma unroll
            for (int k = 0; k < 4; k++)
                pred_acc5(g.y, k, s01[k], s23[k], t01[k], t23[k], cnt[k], sa, sc, ta, tc);
        }
        {
            u64 sa = packf2(a1.z, a2.z), sc = packf2(a3.z, a4.z);
            u64 ta = packf2(b1.z, b2.z), tc = packf2(b3.z, b4.z);
            addf2(sC01, sa); addf2(sC23, sc); addf2(tC01, ta); addf2(tC23, tc);
#pragma unroll
            for (int k = 0; k < 4; k++)
                pred_acc5(g.z, k, s01[k], s23[k], t01[k], t23[k], cnt[k], sa, sc, ta, tc);
        }
        {
            u64 sa = packf2(a1.w, a2.w), sc = packf2(a3.w, a4.w);
            u64 ta = packf2(b1.w, b2.w), tc = packf2(b3.w, b4.w);
            addf2(sC01, sa); addf2(sC23, sc); addf2(tC01, ta); addf2(tC23, tc);
#pragma unroll
            for (int k = 0; k < 4; k++)
                pred_acc5(g.w, k, s01[k], s23[k], t01[k], t23[k], cnt[k], sa, sc, ta, tc);
        }
    }

    // ---- unpack to 44 scalars ----
    float v[44];
#pragma unroll
    for (int k = 0; k < 4; k++) {
        unpackf2(s01[k], v[k * 4 + 0], v[k * 4 + 1]);
        unpackf2(s23[k], v[k * 4 + 2], v[k * 4 + 3]);
        unpackf2(t01[k], v[20 + k * 4 + 0], v[20 + k * 4 + 1]);
        unpackf2(t23[k], v[20 + k * 4 + 2], v[20 + k * 4 + 3]);
        v[40 + k] = cnt[k];
    }
    unpackf2(sC01, v[16], v[17]);
    unpackf2(sC23, v[18], v[19]);
    unpackf2(tC01, v[36], v[37]);
    unpackf2(tC23, v[38], v[39]);

    // ---- warp reduction (deterministic tree), 44 values ----
    const unsigned FULL = 0xffffffffu;
#pragma unroll
    for (int off = 16; off > 0; off >>= 1) {
#pragma unroll
        for (int q = 0; q < 44; q++)
            v[q] += __shfl_down_sync(FULL, v[q], off);
    }

    __shared__ float red[4][45];
    __shared__ bool is_last;
    const int w = threadIdx.x >> 5;
    const int lane = threadIdx.x & 31;
    if (lane == 0) {
#pragma unroll
        for (int q = 0; q < 44; q++) red[w][q] = v[q];
    }
    __syncthreads();

    if (threadIdx.x < 44) {
        float s = 0.f;
#pragma unroll
        for (int ww = 0; ww < 4; ww++) s += red[ww][threadIdx.x];
        atomicAdd(&g_acc[b][threadIdx.x], (double)s);
    }
    __syncthreads();

    // ---- last-block ticket: the final arriver runs the epilogue ----
    if (threadIdx.x == 0) {
        __threadfence();
        unsigned int old = atomicAdd(&g_count, 1u);
        is_last = (old == (unsigned)(NBLK_ - 1));
    }
    __syncthreads();
    if (!is_last) return;
    __threadfence();

    if (threadIdx.x < 32) {
        const int t = threadIdx.x;
        double my = 0.0;

        if (t < 10) {
            const int k = t >> 1;   // class 0..4
            const int bb = t & 1;   // batch

            // nvox summed over BOTH batches (onehot summed over axes 1..4,
            // axis 1 = batch), shared by both batches' averages.
            double n0 = g_acc[0][40] + g_acc[1][40];
            double n1 = g_acc[0][41] + g_acc[1][41];
            double n2 = g_acc[0][42] + g_acc[1][42];
            double n3 = g_acc[0][43] + g_acc[1][43];
            double nvox;
            if      (k == 0) nvox = n0;
            else if (k == 1) nvox = n1;
            else if (k == 2) nvox = n2;
            else if (k == 3) nvox = n3;
            else             nvox = 2.0 * (double)DHW_ - (n0 + n1 + n2 + n3);

            double inv = 1.0 / ((nvox + 1e-6) * 2.0);  // /(nvox+eps)/temperature

            const double* A = g_acc[bb];
            double sl[4], tl[4];
#pragma unroll
            for (int c = 0; c < 4; c++) {
                double ssum, tsum;
                if (k < 4) {
                    ssum = A[k * 4 + c];
                    tsum = A[20 + k * 4 + c];
                } else {
                    ssum = A[16 + c] - (A[c] + A[4 + c] + A[8 + c] + A[12 + c]);
                    tsum = A[36 + c] - (A[20 + c] + A[24 + c] + A[28 + c] + A[32 + c]);
                }
                sl[c] = ssum * inv;
                tl[c] = tsum * inv;
            }
            double ms = sl[0], mt = tl[0];
#pragma unroll
            for (int c = 1; c < 4; c++) {
                if (sl[c] > ms) ms = sl[c];
                if (tl[c] > mt) mt = tl[c];
            }
            double esx[4], etx[4], es = 0.0, et = 0.0;
#pragma unroll
            for (int c = 0; c < 4; c++) {
                esx[c] = fast_exp_small(sl[c] - ms);
                etx[c] = fast_exp_small(tl[c] - mt);
                es += esx[c];
                et += etx[c];
            }
            double lses = ms + fast_log_near4(es);
            double lset = mt + fast_log_near4(et);
            double ies = 1.0 / es, iet = 1.0 / et;
#pragma unroll
            for (int c = 0; c < 4; c++) {
                double d = (tl[c] - lset) - (sl[c] - lses);  // tlp - slp
                my += (etx[c] * iet - esx[c] * ies) * d;     // pt*d - ps*d
            }
        }

#pragma unroll
        for (int off = 16; off > 0; off >>= 1)
            my += __shfl_down_sync(FULL, my, off);

        if (t == 0) {
            // /batch(2) per KL, *0.5 pair average, mean over 5 classes => /20
            out[0] = (float)(my / 20.0);
            g_count = 0;
        }
        // Re-zero scratch for the next invocation / graph replay.
        double* p = (double*)g_acc;
        for (int j = t; j < B_ * 44; j += 32) p[j] = 0.0;
    }
}

extern "C" void kernel_launch(void* const* d_in, const int* in_sizes, int n_in,
                              void* d_out, int out_size) {
    const float* src = (const float*)d_in[0];
    const float* tgt = (const float*)d_in[1];
    const int* gt = (const int*)d_in[2];
    float* out = (float*)d_out;

    dim3 grid(GRIDX_, B_);
    kd_fused_kernel<<<grid, THREADS_>>>(src, tgt, gt, out);
}

// round 14
// speedup vs baseline: 1.0520x; 1.0520x over previous
#include <cuda_runtime.h>
#include <cuda_bf16.h>

// Problem constants
#define B_      2
#define NC_     5
#define DHW_    2457600            // 96*160*160
#define N4_     (DHW_/4)           // 614400 float4 groups per (b, channel)
#define GRIDX_  148
#define STRIDE_ (GRIDX_ * 256)     // 37888 threads per (b,h) slice
#define NBLK_   (GRIDX_ * 4)       // 592 blocks = 148 SMs x 4 CTAs: one wave

// Scratch: [by][j], by = b*2 + h (h: 0=source, 1=target)
// j: 0..15 = sum(k, ch) for k=0..3 (j = k*4 + c, c = ch-1)
//    16..19 = per-channel totals (all classes)   20..23 = counts k=0..3
// Class-4 sums/counts derived by subtraction in the epilogue.
__device__ double g_acc[4][24];
__device__ unsigned int g_count = 0;

typedef unsigned long long u64;

__device__ __forceinline__ u64 packf2(float lo, float hi) {
    u64 r;
    asm("mov.b64 %0, {%1, %2};" : "=l"(r) : "f"(lo), "f"(hi));
    return r;
}
__device__ __forceinline__ void unpackf2(u64 v, float& lo, float& hi) {
    asm("mov.b64 {%0, %1}, %2;" : "=f"(lo), "=f"(hi) : "l"(v));
}
__device__ __forceinline__ void addf2(u64& a, u64 b) {
    asm("add.rn.f32x2 %0, %0, %1;" : "+l"(a) : "l"(b));
}
// If (g == k): a01 += v01 (packed), a23 += v23 (packed), n += 1.0f
__device__ __forceinline__ void pred_acc(u64& a01, u64& a23, float& n,
                                         int g, int k, u64 v01, u64 v23) {
    asm("{\n\t"
        ".reg .pred p;\n\t"
        "setp.eq.s32 p, %3, %4;\n\t"
        "@p add.rn.f32x2 %0, %0, %5;\n\t"
        "@p add.rn.f32x2 %1, %1, %6;\n\t"
        "@p add.f32 %2, %2, 0f3F800000;\n\t"
        "}"
        : "+l"(a01), "+l"(a23), "+f"(n)
        : "r"(g), "r"(k), "l"(v01), "l"(v23));
}

// exp(u) for tiny |u| via degree-6 Taylor; libm fallback for robustness.
__device__ __forceinline__ double fast_exp_small(double u) {
    if (fabs(u) > 0.125) return exp(u);
    double r = 1.0 / 720.0;
    r = fma(r, u, 1.0 / 120.0);
    r = fma(r, u, 1.0 / 24.0);
    r = fma(r, u, 1.0 / 6.0);
    r = fma(r, u, 0.5);
    r = fma(r, u, 1.0);
    r = fma(r, u, 1.0);
    return r;
}

// log(es) for es near 4: ln4 + 2*atanh(w), w = v/(2+v), v = (es-4)/4.
__device__ __forceinline__ double fast_log_near4(double es) {
    double v = (es - 4.0) * 0.25;
    if (fabs(v) > 0.125) return log(es);
    double w = v / (2.0 + v);
    double w2 = w * w;
    double r = 1.0 / 7.0;
    r = fma(r, w2, 1.0 / 5.0);
    r = fma(r, w2, 1.0 / 3.0);
    r = fma(r, w2, 1.0);
    return fma(2.0 * w, r, 1.3862943611198906188);  // + ln(4)
}

__global__ __launch_bounds__(256, 4)
void kd_fused_kernel(const float* __restrict__ src,
                     const float* __restrict__ tgt,
                     const int* __restrict__ gt,
                     float* __restrict__ out) {
    const int by = blockIdx.y;
    const int b = by >> 1;
    const int h = by & 1;

    // Packed accumulators: acc01[k] = (ch1, ch2), acc23[k] = (ch3, ch4)
    u64 acc01[4], acc23[4], accC01, accC23;
    float accN[4];
#pragma unroll
    for (int k = 0; k < 4; k++) { acc01[k] = 0ull; acc23[k] = 0ull; accN[k] = 0.f; }
    accC01 = 0ull; accC23 = 0ull;

    const float* base = (h ? tgt : src) + (size_t)b * NC_ * DHW_;
    const float4* p1 = (const float4*)(base + 1 * (size_t)DHW_);
    const float4* p2 = (const float4*)(base + 2 * (size_t)DHW_);
    const float4* p3 = (const float4*)(base + 3 * (size_t)DHW_);
    const float4* p4 = (const float4*)(base + 4 * (size_t)DHW_);
    const int4* g4 = (const int4*)(gt + (size_t)b * DHW_);

    for (int i = blockIdx.x * 256 + threadIdx.x; i < N4_; i += STRIDE_) {
        // Default cache policy (.ca) — the ONLY change vs the 41.1us champion.
        int4   g  = __ldg(g4 + i);
        float4 v1 = p1[i];
        float4 v2 = p2[i];
        float4 v3 = p3[i];
        float4 v4 = p4[i];

        {
            u64 a = packf2(v1.x, v2.x), c = packf2(v3.x, v4.x);
            addf2(accC01, a); addf2(accC23, c);
#pragma unroll
            for (int k = 0; k < 4; k++) pred_acc(acc01[k], acc23[k], accN[k], g.x, k, a, c);
        }
        {
            u64 a = packf2(v1.y, v2.y), c = packf2(v3.y, v4.y);
            addf2(accC01, a); addf2(accC23, c);
#pragma unroll
            for (int k = 0; k < 4; k++) pred_acc(acc01[k], acc23[k], accN[k], g.y, k, a, c);
        }
        {
            u64 a = packf2(v1.z, v2.z), c = packf2(v3.z, v4.z);
            addf2(accC01, a); addf2(accC23, c);
#pragma unroll
            for (int k = 0; k < 4; k++) pred_acc(acc01[k], acc23[k], accN[k], g.z, k, a, c);
        }
        {
            u64 a = packf2(v1.w, v2.w), c = packf2(v3.w, v4.w);
            addf2(accC01, a); addf2(accC23, c);
#pragma unroll
            for (int k = 0; k < 4; k++) pred_acc(acc01[k], acc23[k], accN[k], g.w, k, a, c);
        }
    }

    // ---- unpack to 24 scalars ----
    float acc[4][4], accC[4];
#pragma unroll
    for (int k = 0; k < 4; k++) {
        unpackf2(acc01[k], acc[k][0], acc[k][1]);
        unpackf2(acc23[k], acc[k][2], acc[k][3]);
    }
    unpackf2(accC01, accC[0], accC[1]);
    unpackf2(accC23, accC[2], accC[3]);

    // ---- warp reduction (deterministic tree), 24 values ----
    const unsigned FULL = 0xffffffffu;
#pragma unroll
    for (int off = 16; off > 0; off >>= 1) {
#pragma unroll
        for (int k = 0; k < 4; k++) {
            accN[k] += __shfl_down_sync(FULL, accN[k], off);
            accC[k] += __shfl_down_sync(FULL, accC[k], off);
#pragma unroll
            for (int c = 0; c < 4; c++)
                acc[k][c] += __shfl_down_sync(FULL, acc[k][c], off);
        }
    }

    __shared__ float red[8][25];
    __shared__ bool is_last;
    const int w = threadIdx.x >> 5;
    const int lane = threadIdx.x & 31;
    if (lane == 0) {
#pragma unroll
        for (int k = 0; k < 4; k++) {
#pragma unroll
            for (int c = 0; c < 4; c++) red[w][k * 4 + c] = acc[k][c];
            red[w][16 + k] = accC[k];
            red[w][20 + k] = accN[k];
        }
    }
    __syncthreads();

    if (threadIdx.x < 24) {
        float s = 0.f;
#pragma unroll
        for (int ww = 0; ww < 8; ww++) s += red[ww][threadIdx.x];
        atomicAdd(&g_acc[by][threadIdx.x], (double)s);
    }
    __syncthreads();

    // ---- last-block ticket: the final arriver runs the epilogue ----
    if (threadIdx.x == 0) {
        __threadfence();
        unsigned int old = atomicAdd(&g_count, 1u);
        is_last = (old == (unsigned)(NBLK_ - 1));
    }
    __syncthreads();
    if (!is_last) return;
    __threadfence();

    if (threadIdx.x < 32) {
        const int t = threadIdx.x;
        double my = 0.0;

        if (t < 10) {
            const int k = t >> 1;   // class 0..4
            const int bb = t & 1;   // batch

            // nvox summed over BOTH batches (onehot summed over axes 1..4,
            // axis 1 = batch), shared by both batches' averages. Counts live
            // in the source halves (by = 0 and 2); class 4 by subtraction.
            double n0 = g_acc[0][20] + g_acc[2][20];
            double n1 = g_acc[0][21] + g_acc[2][21];
            double n2 = g_acc[0][22] + g_acc[2][22];
            double n3 = g_acc[0][23] + g_acc[2][23];
            double nvox;
            if      (k == 0) nvox = n0;
            else if (k == 1) nvox = n1;
            else if (k == 2) nvox = n2;
            else if (k == 3) nvox = n3;
            else             nvox = 2.0 * (double)DHW_ - (n0 + n1 + n2 + n3);

            double inv = 1.0 / ((nvox + 1e-6) * 2.0);  // /(nvox+eps)/temperature

            const double* S = g_acc[bb * 2 + 0];
            const double* T = g_acc[bb * 2 + 1];
            double sl[4], tl[4];
#pragma unroll
            for (int c = 0; c < 4; c++) {
                double ssum, tsum;
                if (k < 4) {
                    ssum = S[k * 4 + c];
                    tsum = T[k * 4 + c];
                } else {
                    ssum = S[16 + c] - (S[c] + S[4 + c] + S[8 + c] + S[12 + c]);
                    tsum = T[16 + c] - (T[c] + T[4 + c] + T[8 + c] + T[12 + c]);
                }
                sl[c] = ssum * inv;
                tl[c] = tsum * inv;
            }
            double ms = sl[0], mt = tl[0];
#pragma unroll
            for (int c = 1; c < 4; c++) {
                if (sl[c] > ms) ms = sl[c];
                if (tl[c] > mt) mt = tl[c];
            }
            double esx[4], etx[4], es = 0.0, et = 0.0;
#pragma unroll
            for (int c = 0; c < 4; c++) {
                esx[c] = fast_exp_small(sl[c] - ms);
                etx[c] = fast_exp_small(tl[c] - mt);
                es += esx[c];
                et += etx[c];
            }
            double lses = ms + fast_log_near4(es);
            double lset = mt + fast_log_near4(et);
            double ies = 1.0 / es, iet = 1.0 / et;
#pragma unroll
            for (int c = 0; c < 4; c++) {
                double d = (tl[c] - lset) - (sl[c] - lses);  // tlp - slp
                my += (etx[c] * iet - esx[c] * ies) * d;     // pt*d - ps*d
            }
        }

#pragma unroll
        for (int off = 16; off > 0; off >>= 1)
            my += __shfl_down_sync(FULL, my, off);

        if (t == 0) {
            // /batch(2) per KL, *0.5 pair average, mean over 5 classes => /20
            out[0] = (float)(my / 20.0);
            g_count = 0;
        }
        // Re-zero scratch for the next invocation / graph replay.
        double* p = (double*)g_acc;
        for (int j = t; j < 4 * 24; j += 32) p[j] = 0.0;
    }
}

extern "C" void kernel_launch(void* const* d_in, const int* in_sizes, int n_in,
                              void* d_out, int out_size) {
    const float* src = (const float*)d_in[0];
    const float* tgt = (const float*)d_in[1];
    const int* gt = (const int*)d_in[2];
    float* out = (float*)d_out;

    dim3 grid(GRIDX_, 4);
    kd_fused_kernel<<<grid, 256>>>(src, tgt, gt, out);
}

// round 15
// speedup vs baseline: 1.1651x; 1.1075x over previous
#include <cuda_runtime.h>
#include <cuda_bf16.h>

// Problem constants
#define B_      2
#define NC_     5
#define DHW_    2457600            // 96*160*160
#define N4_     (DHW_/4)           // 614400 float4 groups per (b, channel)
#define GRIDX_  148
#define STRIDE_ (GRIDX_ * 256)     // 37888 threads per (b,h) slice
#define NBLK_   (GRIDX_ * 4)       // 592 blocks = 148 SMs x 4 CTAs: one wave

// Scratch: [by][j], by = b*2 + h (h: 0=source, 1=target)
// j: 0..15 = sum(k, ch) for k=0..3 (j = k*4 + c, c = ch-1)
//    16..19 = per-channel totals (all classes)   20..23 = counts k=0..3
// Class-4 sums/counts derived by subtraction in the epilogue.
__device__ double g_acc[4][24];
__device__ unsigned int g_count = 0;

typedef unsigned long long u64;

__device__ __forceinline__ u64 packf2(float lo, float hi) {
    u64 r;
    asm("mov.b64 %0, {%1, %2};" : "=l"(r) : "f"(lo), "f"(hi));
    return r;
}
__device__ __forceinline__ void unpackf2(u64 v, float& lo, float& hi) {
    asm("mov.b64 {%0, %1}, %2;" : "=f"(lo), "=f"(hi) : "l"(v));
}
__device__ __forceinline__ void addf2(u64& a, u64 b) {
    asm("add.rn.f32x2 %0, %0, %1;" : "+l"(a) : "l"(b));
}
// If (g == k): a01 += v01 (packed), a23 += v23 (packed), n += 1.0f
__device__ __forceinline__ void pred_acc(u64& a01, u64& a23, float& n,
                                         int g, int k, u64 v01, u64 v23) {
    asm("{\n\t"
        ".reg .pred p;\n\t"
        "setp.eq.s32 p, %3, %4;\n\t"
        "@p add.rn.f32x2 %0, %0, %5;\n\t"
        "@p add.rn.f32x2 %1, %1, %6;\n\t"
        "@p add.f32 %2, %2, 0f3F800000;\n\t"
        "}"
        : "+l"(a01), "+l"(a23), "+f"(n)
        : "r"(g), "r"(k), "l"(v01), "l"(v23));
}

// exp(u) for tiny |u| via degree-6 Taylor; libm fallback for robustness.
__device__ __forceinline__ double fast_exp_small(double u) {
    if (fabs(u) > 0.125) return exp(u);
    double r = 1.0 / 720.0;
    r = fma(r, u, 1.0 / 120.0);
    r = fma(r, u, 1.0 / 24.0);
    r = fma(r, u, 1.0 / 6.0);
    r = fma(r, u, 0.5);
    r = fma(r, u, 1.0);
    r = fma(r, u, 1.0);
    return r;
}

// log(es) for es near 4: ln4 + 2*atanh(w), w = v/(2+v), v = (es-4)/4.
__device__ __forceinline__ double fast_log_near4(double es) {
    double v = (es - 4.0) * 0.25;
    if (fabs(v) > 0.125) return log(es);
    double w = v / (2.0 + v);
    double w2 = w * w;
    double r = 1.0 / 7.0;
    r = fma(r, w2, 1.0 / 5.0);
    r = fma(r, w2, 1.0 / 3.0);
    r = fma(r, w2, 1.0);
    return fma(2.0 * w, r, 1.3862943611198906188);  // + ln(4)
}

__global__ __launch_bounds__(256, 4)
void kd_fused_kernel(const float* __restrict__ src,
                     const float* __restrict__ tgt,
                     const int* __restrict__ gt,
                     float* __restrict__ out) {
    const int by = blockIdx.y;
    const int b = by >> 1;
    const int h = by & 1;

    // Packed accumulators: acc01[k] = (ch1, ch2), acc23[k] = (ch3, ch4)
    u64 acc01[4], acc23[4], accC01, accC23;
    float accN[4];
#pragma unroll
    for (int k = 0; k < 4; k++) { acc01[k] = 0ull; acc23[k] = 0ull; accN[k] = 0.f; }
    accC01 = 0ull; accC23 = 0ull;

    const float* base = (h ? tgt : src) + (size_t)b * NC_ * DHW_;
    const float4* p1 = (const float4*)(base + 1 * (size_t)DHW_);
    const float4* p2 = (const float4*)(base + 2 * (size_t)DHW_);
    const float4* p3 = (const float4*)(base + 3 * (size_t)DHW_);
    const float4* p4 = (const float4*)(base + 4 * (size_t)DHW_);
    const int4* g4 = (const int4*)(gt + (size_t)b * DHW_);

    for (int i = blockIdx.x * 256 + threadIdx.x; i < N4_; i += STRIDE_) {
        int4   g  = __ldg(g4 + i);    // re-read across halves -> L2-cacheable
        float4 v1 = __ldcs(p1 + i);   // logits: read-once, stream (evict-first)
        float4 v2 = __ldcs(p2 + i);
        float4 v3 = __ldcs(p3 + i);
        float4 v4 = __ldcs(p4 + i);

        {
            u64 a = packf2(v1.x, v2.x), c = packf2(v3.x, v4.x);
            addf2(accC01, a); addf2(accC23, c);
#pragma unroll
            for (int k = 0; k < 4; k++) pred_acc(acc01[k], acc23[k], accN[k], g.x, k, a, c);
        }
        {
            u64 a = packf2(v1.y, v2.y), c = packf2(v3.y, v4.y);
            addf2(accC01, a); addf2(accC23, c);
#pragma unroll
            for (int k = 0; k < 4; k++) pred_acc(acc01[k], acc23[k], accN[k], g.y, k, a, c);
        }
        {
            u64 a = packf2(v1.z, v2.z), c = packf2(v3.z, v4.z);
            addf2(accC01, a); addf2(accC23, c);
#pragma unroll
            for (int k = 0; k < 4; k++) pred_acc(acc01[k], acc23[k], accN[k], g.z, k, a, c);
        }
        {
            u64 a = packf2(v1.w, v2.w), c = packf2(v3.w, v4.w);
            addf2(accC01, a); addf2(accC23, c);
#pragma unroll
            for (int k = 0; k < 4; k++) pred_acc(acc01[k], acc23[k], accN[k], g.w, k, a, c);
        }
    }

    // ---- unpack to 24 scalars ----
    float acc[4][4], accC[4];
#pragma unroll
    for (int k = 0; k < 4; k++) {
        unpackf2(acc01[k], acc[k][0], acc[k][1]);
        unpackf2(acc23[k], acc[k][2], acc[k][3]);
    }
    unpackf2(accC01, accC[0], accC[1]);
    unpackf2(accC23, accC[2], accC[3]);

    // ---- warp reduction (deterministic tree), 24 values ----
    const unsigned FULL = 0xffffffffu;
#pragma unroll
    for (int off = 16; off > 0; off >>= 1) {
#pragma unroll
        for (int k = 0; k < 4; k++) {
            accN[k] += __shfl_down_sync(FULL, accN[k], off);
            accC[k] += __shfl_down_sync(FULL, accC[k], off);
#pragma unroll
            for (int c = 0; c < 4; c++)
                acc[k][c] += __shfl_down_sync(FULL, acc[k][c], off);
        }
    }

    __shared__ float red[8][25];
    __shared__ bool is_last;
    const int w = threadIdx.x >> 5;
    const int lane = threadIdx.x & 31;
    if (lane == 0) {
#pragma unroll
        for (int k = 0; k < 4; k++) {
#pragma unroll
            for (int c = 0; c < 4; c++) red[w][k * 4 + c] = acc[k][c];
            red[w][16 + k] = accC[k];
            red[w][20 + k] = accN[k];
        }
    }
    __syncthreads();

    if (threadIdx.x < 24) {
        float s = 0.f;
#pragma unroll
        for (int ww = 0; ww < 8; ww++) s += red[ww][threadIdx.x];
        atomicAdd(&g_acc[by][threadIdx.x], (double)s);
    }
    __syncthreads();

    // ---- last-block ticket: the final arriver runs the epilogue ----
    if (threadIdx.x == 0) {
        __threadfence();
        unsigned int old = atomicAdd(&g_count, 1u);
        is_last = (old == (unsigned)(NBLK_ - 1));
    }
    __syncthreads();
    if (!is_last) return;
    __threadfence();

    if (threadIdx.x < 32) {
        const int t = threadIdx.x;
        double my = 0.0;

        if (t < 10) {
            const int k = t >> 1;   // class 0..4
            const int bb = t & 1;   // batch

            // nvox summed over BOTH batches (onehot summed over axes 1..4,
            // axis 1 = batch), shared by both batches' averages. Counts live
            // in the source halves (by = 0 and 2); class 4 by subtraction.
            double n0 = g_acc[0][20] + g_acc[2][20];
            double n1 = g_acc[0][21] + g_acc[2][21];
            double n2 = g_acc[0][22] + g_acc[2][22];
            double n3 = g_acc[0][23] + g_acc[2][23];
            double nvox;
            if      (k == 0) nvox = n0;
            else if (k == 1) nvox = n1;
            else if (k == 2) nvox = n2;
            else if (k == 3) nvox = n3;
            else             nvox = 2.0 * (double)DHW_ - (n0 + n1 + n2 + n3);

            double inv = 1.0 / ((nvox + 1e-6) * 2.0);  // /(nvox+eps)/temperature

            const double* S = g_acc[bb * 2 + 0];
            const double* T = g_acc[bb * 2 + 1];
            double sl[4], tl[4];
#pragma unroll
            for (int c = 0; c < 4; c++) {
                double ssum, tsum;
                if (k < 4) {
                    ssum = S[k * 4 + c];
                    tsum = T[k * 4 + c];
                } else {
                    ssum = S[16 + c] - (S[c] + S[4 + c] + S[8 + c] + S[12 + c]);
                    tsum = T[16 + c] - (T[c] + T[4 + c] + T[8 + c] + T[12 + c]);
                }
                sl[c] = ssum * inv;
                tl[c] = tsum * inv;
            }
            double ms = sl[0], mt = tl[0];
#pragma unroll
            for (int c = 1; c < 4; c++) {
                if (sl[c] > ms) ms = sl[c];
                if (tl[c] > mt) mt = tl[c];
            }
            double esx[4], etx[4], es = 0.0, et = 0.0;
#pragma unroll
            for (int c = 0; c < 4; c++) {
                esx[c] = fast_exp_small(sl[c] - ms);
                etx[c] = fast_exp_small(tl[c] - mt);
                es += esx[c];
                et += etx[c];
            }
            double lses = ms + fast_log_near4(es);
            double lset = mt + fast_log_near4(et);
            double ies = 1.0 / es, iet = 1.0 / et;
#pragma unroll
            for (int c = 0; c < 4; c++) {
                double d = (tl[c] - lset) - (sl[c] - lses);  // tlp - slp
                my += (etx[c] * iet - esx[c] * ies) * d;     // pt*d - ps*d
            }
        }

#pragma unroll
        for (int off = 16; off > 0; off >>= 1)
            my += __shfl_down_sync(FULL, my, off);

        if (t == 0) {
            // /batch(2) per KL, *0.5 pair average, mean over 5 classes => /20
            out[0] = (float)(my / 20.0);
            g_count = 0;
        }
        // Re-zero scratch for the next invocation / graph replay.
        double* p = (double*)g_acc;
        for (int j = t; j < 4 * 24; j += 32) p[j] = 0.0;
    }
}

extern "C" void kernel_launch(void* const* d_in, const int* in_sizes, int n_in,
                              void* d_out, int out_size) {
    const float* src = (const float*)d_in[0];
    const float* tgt = (const float*)d_in[1];
    const int* gt = (const int*)d_in[2];
    float* out = (float*)d_out;

    dim3 grid(GRIDX_, 4);
    kd_fused_kernel<<<grid, 256>>>(src, tgt, gt, out);
}